// round 16
// baseline (speedup 1.0000x reference)
#include <cuda_runtime.h>
#include <cuda_bf16.h>
#include <cstdint>

#define NB    4
#define NSEQ  512
#define DIMK  64
#define NCH   256
#define NT    512

// device scratch
__device__ float d_Wq  [DIMK * NCH];
__device__ float d_Wk  [DIMK * NCH];
__device__ float d_cvec[NCH];
__device__ float d_qk1 [NB * NSEQ * NCH];
__device__ float d_v   [NB * NSEQ * DIMK];
// B fragments, fragment-major: [ng][q(16)][lane(32)][uint4]  (32KB, L2-resident)
__device__ uint4 d_Bpk[4 * 16 * 32];
// kk1 (k@W1, bf16) pre-packed per-lane fragment order:
// u32 idx = (cc*32 + lane)*4 + n8 (+128 for rh=1), cc = ((b*4+mg)*4+ng)*16 + t*4+mb*2+ch
__device__ uint32_t d_kkp[NB * NSEQ * NCH / 2];

__device__ __forceinline__ uint32_t smem_to_u32(const void* p) {
    uint32_t a;
    asm("{ .reg .u64 t; cvta.to.shared.u64 t, %1; cvt.u32.u64 %0, t; }" : "=r"(a) : "l"(p));
    return a;
}
__device__ __forceinline__ void ldsm4(uint32_t& r0, uint32_t& r1, uint32_t& r2, uint32_t& r3, uint32_t addr) {
    asm volatile("ldmatrix.sync.aligned.m8n8.x4.shared.b16 {%0,%1,%2,%3}, [%4];"
                 : "=r"(r0), "=r"(r1), "=r"(r2), "=r"(r3) : "r"(addr));
}
__device__ __forceinline__ void mma16816(float* c, const uint32_t* a, uint32_t b0, uint32_t b1) {
    asm volatile("mma.sync.aligned.m16n8k16.row.col.f32.bf16.bf16.f32 "
                 "{%0,%1,%2,%3}, {%4,%5,%6,%7}, {%8,%9}, {%0,%1,%2,%3};"
                 : "+f"(c[0]), "+f"(c[1]), "+f"(c[2]), "+f"(c[3])
                 : "r"(a[0]), "r"(a[1]), "r"(a[2]), "r"(a[3]), "r"(b0), "r"(b1));
}

// smem byte layout: full A (p bf16 [512][64], swizzled 128B rows) = 64KB; ext after.
#define OFF_EXT  65536
#define SMEM_TOTAL 93696    // 65536 + 7040*4
// ext float indices
#define E_PJ    0        // 1536: pos_all [3][512]
#define E_QS    1536     // 256
#define E_W2S   1792     // 256
#define E_W1S   2048     // 192
#define E_B1S   2240     // 64
#define E_SIMS  2304     // 512
#define E_SPART 2816     // 2048: [4 ng][512]
#define E_GPART 4864     // 1024: [16 jg][64]
#define E_RPART 5888     // 1024
#define E_GS    6912     // 64
#define E_RED   6976     // 64

// -------------------- K0a: fold weights + write B pack directly --------------------
__global__ void prep_mats(const float* __restrict__ w_qkv, const float* __restrict__ pos_w2,
                          const float* __restrict__ pos_b2, const float* __restrict__ attn_w1,
                          const float* __restrict__ attn_b1) {
    int c = threadIdx.x, bid = blockIdx.x;
    if (bid == 192) {
        float acc = attn_b1[c];
        #pragma unroll 8
        for (int d = 0; d < DIMK; d++) acc = fmaf(pos_b2[d], attn_w1[d * NCH + c], acc);
        d_cvec[c] = acc;
        return;
    }
    int m = bid >> 6, k = bid & 63;
    const float* src = (m == 0) ? (pos_w2 + k * 64) : (m == 1) ? (w_qkv + k * 192) : (w_qkv + k * 192 + 64);
    float acc = 0.f;
    #pragma unroll 8
    for (int d = 0; d < DIMK; d++) acc = fmaf(src[d], attn_w1[d * NCH + c], acc);
    if (m == 0) {
        // write bf16(M[k][c]) directly into its d_Bpk fragment byte
        int n = c;
        int ng = n >> 6, ch = (n >> 5) & 1, nb = (n >> 4) & 1;
        int lane = ((n & 7) << 2) | ((k >> 1) & 3);
        int i = (((n >> 3) & 1) << 1) | ((k >> 3) & 1);
        int ks = k >> 4;
        int cf = ch * 32 + nb * 16 + ks * 4 + i;
        int e = ng * 2048 + (cf >> 2) * 128 + lane * 4 + (cf & 3);
        *((__nv_bfloat16*)d_Bpk + e * 2 + (k & 1)) = __float2bfloat16(acc);
    } else {
        float* dst = (m == 1) ? d_Wq : d_Wk;
        dst[k * NCH + c] = acc;
    }
}

// -------------------- K0b: projections (kk written pre-packed) --------------------
__global__ __launch_bounds__(256) void proj_kernel(const float* __restrict__ x,
                                                   const float* __restrict__ w_qkv) {
    __shared__ float xs[16][64];
    int c = threadIdx.x;
    int row0 = blockIdx.x * 16;
    for (int idx = c; idx < 16 * 64; idx += 256) xs[idx >> 6][idx & 63] = x[row0 * 64 + idx];
    __syncthreads();
    float accq[16], acck[16];
    #pragma unroll
    for (int r = 0; r < 16; r++) { accq[r] = 0.f; acck[r] = 0.f; }
    for (int k = 0; k < 64; k++) {
        float wq = d_Wq[k * NCH + c], wk = d_Wk[k * NCH + c];
        #pragma unroll
        for (int r = 0; r < 16; r++) {
            float xv = xs[r][k];
            accq[r] = fmaf(xv, wq, accq[r]);
            acck[r] = fmaf(xv, wk, acck[r]);
        }
    }
    float cv = d_cvec[c];
    int ng2 = c >> 6, ch2 = (c >> 5) & 1, n8 = (c >> 3) & 3, lq = (c >> 1) & 3, byt = c & 1;
    #pragma unroll
    for (int r = 0; r < 16; r++) {
        int row = row0 + r;
        d_qk1[(size_t)row * NCH + c] = accq[r] + cv;
        int bb2 = row >> 9, j = row & 511;
        int t = j >> 7, mg2 = (j >> 5) & 3, mb = (j >> 4) & 1, rh = (j >> 3) & 1;
        int lane2 = ((j & 7) << 2) | lq;
        int bt = ((bb2 * 4 + mg2) * 4 + ng2) * 4 + t;
        size_t u32idx = ((size_t)((((bt * 2 + mb) * 2 + ch2) * 2 + rh) * 32) + lane2) * 4 + n8;
        *((__nv_bfloat16*)d_kkp + u32idx * 2 + byt) = __float2bfloat16(acck[r]);
    }
    int d = c & 63, rg = c >> 6;
    for (int r = rg; r < 16; r += 4) {
        float acc = 0.f;
        #pragma unroll 8
        for (int k = 0; k < 64; k++) acc = fmaf(xs[r][k], w_qkv[k * 192 + 128 + d], acc);
        d_v[(size_t)(row0 + r) * 64 + d] = acc;
    }
}

// -------------------- K1: fused attention (R15 + kk prefetch + barrier fuse) ------
__global__ __launch_bounds__(NT, 1) void pt_main(const float* __restrict__ pos,
                                                 const float* __restrict__ pos_w1,
                                                 const float* __restrict__ pos_b1,
                                                 const float* __restrict__ pos_w2,
                                                 const float* __restrict__ pos_b2,
                                                 const float* __restrict__ attn_w2,
                                                 float* __restrict__ out) {
    extern __shared__ __align__(1024) char smc[];
    float* ext = (float*)(smc + OFF_EXT);
    float* pjall = ext + E_PJ; float* qs = ext + E_QS; float* w2s = ext + E_W2S;
    float* w1s = ext + E_W1S; float* b1s = ext + E_B1S; float* sims = ext + E_SIMS;
    float* spart = ext + E_SPART; float* gpart = ext + E_GPART; float* rpart = ext + E_RPART;
    float* gs = ext + E_GS; float* red = ext + E_RED;

    uint32_t sbase = smem_to_u32(smc);
    int tid = threadIdx.x, wid = tid >> 5, lane = tid & 31;
    int bi = blockIdx.x, b = bi >> 9;

    // stage block-invariant data + all pos_j
    for (int idx = tid; idx < 1536; idx += NT) {
        int d = idx >> 9, j = idx & 511;
        pjall[d * 512 + j] = pos[((size_t)b * NSEQ + j) * 3 + d];
    }
    if (tid < 256)      { qs[tid] = d_qk1[(size_t)bi * NCH + tid]; w2s[tid] = attn_w2[tid]; }
    else if (tid < 448) { w1s[tid - 256] = pos_w1[tid - 256]; }
    else                { b1s[tid - 448] = pos_b1[tid - 448]; }
    float px = pos[bi * 3 + 0], py = pos[bi * 3 + 1], pz = pos[bi * 3 + 2];

    // warp tiling: mg = m-group (32 rows, 4 groups), ng = n-group (64 cols, 4 groups)
    int mg = wid >> 2, ng = wid & 3;
    int m0 = mg * 32, n0base = ng * 64;
    int r8 = lane & 7, g = lane >> 3;
    int rowAoff = (g & 1) << 3, kcA = g >> 1;
    int rq = lane >> 2, t4 = lane & 3;

    // load B fragments from global, coalesced: [ng][q][lane]
    uint32_t Breg[2][2][4][4];
    {
        const uint4* bp = d_Bpk + (ng << 9) + lane;
        uint4* br = (uint4*)&Breg[0][0][0][0];
        #pragma unroll
        for (int q = 0; q < 16; q++) br[q] = bp[q << 5];
    }
    __syncthreads();

    // ---------------- p-gen: fixed k-pair per thread, weights hoisted ----------------
    {
        int kp = tid & 31;
        int k = kp << 1;
        float wx0 = w1s[k],     wy0 = w1s[64 + k],     wz0 = w1s[128 + k],     bb0 = b1s[k];
        float wx1 = w1s[k + 1], wy1 = w1s[64 + k + 1], wz1 = w1s[128 + k + 1], bb1 = b1s[k + 1];
        unsigned swk = ((kp & 3) << 2);
        for (int j = tid >> 5; j < 512; j += 16) {
            float rx = px - pjall[j], ry = py - pjall[512 + j], rz = pz - pjall[1024 + j];
            float v0 = fmaf(rx, wx0, fmaf(ry, wy0, fmaf(rz, wz0, bb0)));
            float v1 = fmaf(rx, wx1, fmaf(ry, wy1, fmaf(rz, wz1, bb1)));
            __nv_bfloat162 hh = __floats2bfloat162_rn(fmaxf(v0, 0.f), fmaxf(v1, 0.f));
            unsigned sw = j * 128 + ((((kp >> 2) ^ (j & 7))) << 4) + swk;
            *(uint32_t*)(smc + sw) = *(uint32_t*)&hh;
        }
    }
    __syncthreads();

    // ---------------- PASS 1: 4 tiles, kk prefetched one combo ahead ----------------
    int K016 = (((b << 2) + mg) * 4 + ng) << 4;
    const uint4* kkbase = (const uint4*)d_kkp;
    uint4 kr0c, kr1c;
    {
        const uint4* kb = kkbase + (size_t)K016 * 64 + lane;
        kr0c = kb[0]; kr1c = kb[32];
    }
    #pragma unroll 1
    for (int t = 0; t < 4; t++) {
        uint32_t Abase = sbase + (t * 128 + m0 + rowAoff + r8) * 128;
        float sm[4] = {0.f, 0.f, 0.f, 0.f};

        #pragma unroll
        for (int mb = 0; mb < 2; mb++) {
            uint32_t ah[4][4];
            #pragma unroll
            for (int ks = 0; ks < 4; ks++) {
                uint32_t axor = (uint32_t)(((2 * ks + kcA) ^ r8) << 4);
                ldsm4(ah[ks][0], ah[ks][1], ah[ks][2], ah[ks][3], Abase + mb * 2048 + axor);
            }
            #pragma unroll
            for (int ch = 0; ch < 2; ch++) {
                int n0 = n0base + ch * 32;
                // prefetch next combo's kk (clamped at the end)
                int c = t * 4 + mb * 2 + ch;
                int cn = (c < 15) ? c + 1 : 15;
                const uint4* kb = kkbase + (size_t)(K016 + cn) * 64 + lane;
                uint4 kr0n = kb[0], kr1n = kb[32];

                float acc[4][4];
                #pragma unroll
                for (int q = 0; q < 4; q++)
                    #pragma unroll
                    for (int r = 0; r < 4; r++) acc[q][r] = 0.f;

                #pragma unroll
                for (int ks = 0; ks < 4; ks++) {
                    #pragma unroll
                    for (int nb = 0; nb < 2; nb++) {
                        mma16816(acc[2 * nb],     ah[ks], Breg[ch][nb][ks][0], Breg[ch][nb][ks][1]);
                        mma16816(acc[2 * nb + 1], ah[ks], Breg[ch][nb][ks][2], Breg[ch][nb][ks][3]);
                    }
                }
                // epilogue for this 32-col chunk
                float s0 = 0.f, s1 = 0.f;
                #pragma unroll
                for (int n8 = 0; n8 < 4; n8++) {
                    int n = n0 + n8 * 8 + t4 * 2;
                    float2 qv = *(const float2*)(qs + n);
                    float2 wv = *(const float2*)(w2s + n);
                    float2 k0 = __bfloat1622float2(*(const __nv_bfloat162*)&((const uint32_t*)&kr0c)[n8]);
                    float2 k1 = __bfloat1622float2(*(const __nv_bfloat162*)&((const uint32_t*)&kr1c)[n8]);
                    s0 = fmaf(fmaxf(acc[n8][0] + qv.x - k0.x, 0.f), wv.x,
                         fmaf(fmaxf(acc[n8][1] + qv.y - k0.y, 0.f), wv.y, s0));
                    s1 = fmaf(fmaxf(acc[n8][2] + qv.x - k1.x, 0.f), wv.x,
                         fmaf(fmaxf(acc[n8][3] + qv.y - k1.y, 0.f), wv.y, s1));
                }
                sm[2 * mb] += s0; sm[2 * mb + 1] += s1;
                kr0c = kr0n; kr1c = kr1n;
            }
        }
        // quad reduce + write per-tile partials (disjoint slots, no barrier)
        #pragma unroll
        for (int q = 0; q < 4; q++) {
            sm[q] += __shfl_xor_sync(0xffffffffu, sm[q], 1);
            sm[q] += __shfl_xor_sync(0xffffffffu, sm[q], 2);
        }
        if (t4 == 0) {
            spart[ng * 512 + t * 128 + m0 + rq]      = sm[0];
            spart[ng * 512 + t * 128 + m0 + rq + 8]  = sm[1];
            spart[ng * 512 + t * 128 + m0 + rq + 16] = sm[2];
            spart[ng * 512 + t * 128 + m0 + rq + 24] = sm[3];
        }
    }
    __syncthreads();

    // ---------------- softmax over 512 sims (reduction fused into read) ----------------
    {
        float s = spart[tid] + spart[512 + tid] + spart[1024 + tid] + spart[1536 + tid];
        float m = s;
        #pragma unroll
        for (int off = 16; off; off >>= 1) m = fmaxf(m, __shfl_xor_sync(0xffffffffu, m, off));
        if (lane == 0) red[wid] = m;
        __syncthreads();
        if (tid < 32) {
            float v = (tid < 16) ? red[tid] : -3.4e38f;
            #pragma unroll
            for (int off = 8; off; off >>= 1) v = fmaxf(v, __shfl_xor_sync(0xffffffffu, v, off));
            if (tid == 0) red[32] = v;
        }
        __syncthreads();
        float e = __expf(s - red[32]);
        float tt = e;
        #pragma unroll
        for (int off = 16; off; off >>= 1) tt += __shfl_xor_sync(0xffffffffu, tt, off);
        if (lane == 0) red[wid] = tt;
        __syncthreads();
        if (tid < 32) {
            float v = (tid < 16) ? red[tid] : 0.f;
            #pragma unroll
            for (int off = 8; off; off >>= 1) v += __shfl_xor_sync(0xffffffffu, v, off);
            if (tid == 0) red[33] = v;
        }
        __syncthreads();
        sims[tid] = e / red[33];
        __syncthreads();
    }

    // ---------------- PASS 2: k-pair per thread; g = a@p, r = a@v ----------------
    {
        int k2 = tid & 31, jg = tid >> 5;
        int k = k2 << 1;
        float wx0 = w1s[k],     wy0 = w1s[64 + k],     wz0 = w1s[128 + k],     bb0 = b1s[k];
        float wx1 = w1s[k + 1], wy1 = w1s[64 + k + 1], wz1 = w1s[128 + k + 1], bb1 = b1s[k + 1];
        float g0 = 0.f, g1 = 0.f, r0 = 0.f, r1 = 0.f;
        const float* vb = d_v + ((size_t)(b << 9) + jg * 32) * 64 + k;
        int j0 = jg * 32;
        #pragma unroll 4
        for (int jj = 0; jj < 32; jj++) {
            int j = j0 + jj;
            float a = sims[j];
            float2 vv = *(const float2*)(vb + jj * 64);
            float rx = px - pjall[j], ry = py - pjall[512 + j], rz = pz - pjall[1024 + j];
            float pv0 = fmaxf(fmaf(rx, wx0, fmaf(ry, wy0, fmaf(rz, wz0, bb0))), 0.f);
            float pv1 = fmaxf(fmaf(rx, wx1, fmaf(ry, wy1, fmaf(rz, wz1, bb1))), 0.f);
            g0 = fmaf(a, pv0, g0); g1 = fmaf(a, pv1, g1);
            r0 = fmaf(a, vv.x, r0); r1 = fmaf(a, vv.y, r1);
        }
        *(float2*)(gpart + jg * 64 + k) = make_float2(g0, g1);
        *(float2*)(rpart + jg * 64 + k) = make_float2(r0, r1);
        __syncthreads();
        float rsum = 0.f;
        if (tid < 64) {
            float gsum = 0.f;
            #pragma unroll
            for (int w = 0; w < 16; w++) { gsum += gpart[w * 64 + tid]; rsum += rpart[w * 64 + tid]; }
            gs[tid] = gsum;
        }
        __syncthreads();
        if (tid < 64) {
            float o = rsum + pos_b2[tid];
            #pragma unroll 8
            for (int kk = 0; kk < 64; kk++) o = fmaf(gs[kk], pos_w2[kk * 64 + tid], o);
            out[(size_t)bi * 64 + tid] = o;
        }
    }
}

// -------------------- launch --------------------
extern "C" void kernel_launch(void* const* d_in, const int* in_sizes, int n_in,
                              void* d_out, int out_size) {
    const float* x       = (const float*)d_in[0];
    const float* pos     = (const float*)d_in[1];
    const float* w_qkv   = (const float*)d_in[2];
    const float* pos_w1  = (const float*)d_in[3];
    const float* pos_b1  = (const float*)d_in[4];
    const float* pos_w2  = (const float*)d_in[5];
    const float* pos_b2  = (const float*)d_in[6];
    const float* attn_w1 = (const float*)d_in[7];
    const float* attn_b1 = (const float*)d_in[8];
    const float* attn_w2 = (const float*)d_in[9];
    // attn_b2 (d_in[10]) cancels in softmax
    float* out = (float*)d_out;

    cudaFuncSetAttribute(pt_main, cudaFuncAttributeMaxDynamicSharedMemorySize, SMEM_TOTAL);

    prep_mats<<<193, 256>>>(w_qkv, pos_w2, pos_b2, attn_w1, attn_b1);
    proj_kernel<<<128, 256>>>(x, w_qkv);
    pt_main<<<NB * NSEQ, NT, SMEM_TOTAL>>>(pos, pos_w1, pos_b1, pos_w2, pos_b2, attn_w2, out);
}

// round 17
// speedup vs baseline: 1.0377x; 1.0377x over previous
#include <cuda_runtime.h>
#include <cuda_bf16.h>
#include <cstdint>

#define NB    4
#define NSEQ  512
#define DIMK  64
#define NCH   256
#define NT    512

// device scratch
__device__ float d_Wq  [DIMK * NCH];
__device__ float d_Wk  [DIMK * NCH];
__device__ float d_cvec[NCH];
__device__ float d_qk1 [NB * NSEQ * NCH];
__device__ float d_v   [NB * NSEQ * DIMK];
// B fragments, fragment-major: [ng][q(16)][lane(32)][uint4]  (32KB, L2-resident)
__device__ uint4 d_Bpk[4 * 16 * 32];
// kk1 (k@W1, bf16) pre-packed per-lane fragment order:
// u32 idx = ((((bt*2+mb)*2+ch)*2+rh)*32 + lane)*4 + n8,  bt = ((b*4+mg)*4+ng)*4+t
__device__ uint32_t d_kkp[NB * NSEQ * NCH / 2];

__device__ __forceinline__ uint32_t smem_to_u32(const void* p) {
    uint32_t a;
    asm("{ .reg .u64 t; cvta.to.shared.u64 t, %1; cvt.u32.u64 %0, t; }" : "=r"(a) : "l"(p));
    return a;
}
__device__ __forceinline__ void ldsm4(uint32_t& r0, uint32_t& r1, uint32_t& r2, uint32_t& r3, uint32_t addr) {
    asm volatile("ldmatrix.sync.aligned.m8n8.x4.shared.b16 {%0,%1,%2,%3}, [%4];"
                 : "=r"(r0), "=r"(r1), "=r"(r2), "=r"(r3) : "r"(addr));
}
__device__ __forceinline__ void mma16816(float* c, const uint32_t* a, uint32_t b0, uint32_t b1) {
    asm volatile("mma.sync.aligned.m16n8k16.row.col.f32.bf16.bf16.f32 "
                 "{%0,%1,%2,%3}, {%4,%5,%6,%7}, {%8,%9}, {%0,%1,%2,%3};"
                 : "+f"(c[0]), "+f"(c[1]), "+f"(c[2]), "+f"(c[3])
                 : "r"(a[0]), "r"(a[1]), "r"(a[2]), "r"(a[3]), "r"(b0), "r"(b1));
}

// smem byte layout: full A (p bf16 [512][64], swizzled 128B rows) = 64KB; ext after.
#define OFF_EXT  65536
#define SMEM_TOTAL 93696    // 65536 + 7040*4
// ext float indices
#define E_PJ    0        // 1536: pos_all [3][512]
#define E_QS    1536     // 256
#define E_W2S   1792     // 256
#define E_W1S   2048     // 192
#define E_B1S   2240     // 64
#define E_SIMS  2304     // 512
#define E_SPART 2816     // 2048: [4 ng][512]
#define E_GPART 4864     // 1024: [16 jg][64]
#define E_RPART 5888     // 1024
#define E_GS    6912     // 64
#define E_RED   6976     // 64

// -------------------- K0a: fold weights + write B pack directly --------------------
__global__ void prep_mats(const float* __restrict__ w_qkv, const float* __restrict__ pos_w2,
                          const float* __restrict__ pos_b2, const float* __restrict__ attn_w1,
                          const float* __restrict__ attn_b1) {
    int c = threadIdx.x, bid = blockIdx.x;
    if (bid == 192) {
        float acc = attn_b1[c];
        #pragma unroll 8
        for (int d = 0; d < DIMK; d++) acc = fmaf(pos_b2[d], attn_w1[d * NCH + c], acc);
        d_cvec[c] = acc;
        return;
    }
    int m = bid >> 6, k = bid & 63;
    const float* src = (m == 0) ? (pos_w2 + k * 64) : (m == 1) ? (w_qkv + k * 192) : (w_qkv + k * 192 + 64);
    float acc = 0.f;
    #pragma unroll 8
    for (int d = 0; d < DIMK; d++) acc = fmaf(src[d], attn_w1[d * NCH + c], acc);
    if (m == 0) {
        // write bf16(M[k][c]) directly into its d_Bpk fragment byte
        int n = c;
        int ng = n >> 6, ch = (n >> 5) & 1, nb = (n >> 4) & 1;
        int lane = ((n & 7) << 2) | ((k >> 1) & 3);
        int i = (((n >> 3) & 1) << 1) | ((k >> 3) & 1);
        int ks = k >> 4;
        int cf = ch * 32 + nb * 16 + ks * 4 + i;
        int e = ng * 2048 + (cf >> 2) * 128 + lane * 4 + (cf & 3);
        *((__nv_bfloat16*)d_Bpk + e * 2 + (k & 1)) = __float2bfloat16(acc);
    } else {
        float* dst = (m == 1) ? d_Wq : d_Wk;
        dst[k * NCH + c] = acc;
    }
}

// -------------------- K0b: projections (kk written pre-packed) --------------------
__global__ __launch_bounds__(256) void proj_kernel(const float* __restrict__ x,
                                                   const float* __restrict__ w_qkv) {
    __shared__ float xs[16][64];
    int c = threadIdx.x;
    int row0 = blockIdx.x * 16;
    for (int idx = c; idx < 16 * 64; idx += 256) xs[idx >> 6][idx & 63] = x[row0 * 64 + idx];
    __syncthreads();
    float accq[16], acck[16];
    #pragma unroll
    for (int r = 0; r < 16; r++) { accq[r] = 0.f; acck[r] = 0.f; }
    for (int k = 0; k < 64; k++) {
        float wq = d_Wq[k * NCH + c], wk = d_Wk[k * NCH + c];
        #pragma unroll
        for (int r = 0; r < 16; r++) {
            float xv = xs[r][k];
            accq[r] = fmaf(xv, wq, accq[r]);
            acck[r] = fmaf(xv, wk, acck[r]);
        }
    }
    float cv = d_cvec[c];
    int ng2 = c >> 6, ch2 = (c >> 5) & 1, n8 = (c >> 3) & 3, lq = (c >> 1) & 3, byt = c & 1;
    #pragma unroll
    for (int r = 0; r < 16; r++) {
        int row = row0 + r;
        d_qk1[(size_t)row * NCH + c] = accq[r] + cv;
        int bb2 = row >> 9, j = row & 511;
        int t = j >> 7, mg2 = (j >> 5) & 3, mb = (j >> 4) & 1, rh = (j >> 3) & 1;
        int lane2 = ((j & 7) << 2) | lq;
        int bt = ((bb2 * 4 + mg2) * 4 + ng2) * 4 + t;
        size_t u32idx = ((size_t)((((bt * 2 + mb) * 2 + ch2) * 2 + rh) * 32) + lane2) * 4 + n8;
        *((__nv_bfloat16*)d_kkp + u32idx * 2 + byt) = __float2bfloat16(acck[r]);
    }
    int d = c & 63, rg = c >> 6;
    for (int r = rg; r < 16; r += 4) {
        float acc = 0.f;
        #pragma unroll 8
        for (int k = 0; k < 64; k++) acc = fmaf(xs[r][k], w_qkv[k * 192 + 128 + d], acc);
        d_v[(size_t)(row0 + r) * 64 + d] = acc;
    }
}

// -------------------- K1: fused attention (R15 body + fused softmax read) ------
__global__ __launch_bounds__(NT, 1) void pt_main(const float* __restrict__ pos,
                                                 const float* __restrict__ pos_w1,
                                                 const float* __restrict__ pos_b1,
                                                 const float* __restrict__ pos_w2,
                                                 const float* __restrict__ pos_b2,
                                                 const float* __restrict__ attn_w2,
                                                 float* __restrict__ out) {
    extern __shared__ __align__(1024) char smc[];
    float* ext = (float*)(smc + OFF_EXT);
    float* pjall = ext + E_PJ; float* qs = ext + E_QS; float* w2s = ext + E_W2S;
    float* w1s = ext + E_W1S; float* b1s = ext + E_B1S; float* sims = ext + E_SIMS;
    float* spart = ext + E_SPART; float* gpart = ext + E_GPART; float* rpart = ext + E_RPART;
    float* gs = ext + E_GS; float* red = ext + E_RED;

    uint32_t sbase = smem_to_u32(smc);
    int tid = threadIdx.x, wid = tid >> 5, lane = tid & 31;
    int bi = blockIdx.x, b = bi >> 9;

    // stage block-invariant data + all pos_j
    for (int idx = tid; idx < 1536; idx += NT) {
        int d = idx >> 9, j = idx & 511;
        pjall[d * 512 + j] = pos[((size_t)b * NSEQ + j) * 3 + d];
    }
    if (tid < 256)      { qs[tid] = d_qk1[(size_t)bi * NCH + tid]; w2s[tid] = attn_w2[tid]; }
    else if (tid < 448) { w1s[tid - 256] = pos_w1[tid - 256]; }
    else                { b1s[tid - 448] = pos_b1[tid - 448]; }
    float px = pos[bi * 3 + 0], py = pos[bi * 3 + 1], pz = pos[bi * 3 + 2];

    // warp tiling: mg = m-group (32 rows, 4 groups), ng = n-group (64 cols, 4 groups)
    int mg = wid >> 2, ng = wid & 3;
    int m0 = mg * 32, n0base = ng * 64;
    int r8 = lane & 7, g = lane >> 3;
    int rowAoff = (g & 1) << 3, kcA = g >> 1;
    int rq = lane >> 2, t4 = lane & 3;

    // load B fragments from global, coalesced: [ng][q][lane]
    uint32_t Breg[2][2][4][4];
    {
        const uint4* bp = d_Bpk + (ng << 9) + lane;
        uint4* br = (uint4*)&Breg[0][0][0][0];
        #pragma unroll
        for (int q = 0; q < 16; q++) br[q] = bp[q << 5];
    }
    __syncthreads();

    // ---------------- p-gen: fixed k-pair per thread, weights hoisted ----------------
    {
        int kp = tid & 31;                 // fixed k-pair (NT multiple of 32)
        int k = kp << 1;
        float wx0 = w1s[k],     wy0 = w1s[64 + k],     wz0 = w1s[128 + k],     bb0 = b1s[k];
        float wx1 = w1s[k + 1], wy1 = w1s[64 + k + 1], wz1 = w1s[128 + k + 1], bb1 = b1s[k + 1];
        unsigned swk = ((kp & 3) << 2);
        for (int j = tid >> 5; j < 512; j += 16) {
            float rx = px - pjall[j], ry = py - pjall[512 + j], rz = pz - pjall[1024 + j];
            float v0 = fmaf(rx, wx0, fmaf(ry, wy0, fmaf(rz, wz0, bb0)));
            float v1 = fmaf(rx, wx1, fmaf(ry, wy1, fmaf(rz, wz1, bb1)));
            __nv_bfloat162 hh = __floats2bfloat162_rn(fmaxf(v0, 0.f), fmaxf(v1, 0.f));
            unsigned sw = j * 128 + ((((kp >> 2) ^ (j & 7))) << 4) + swk;
            *(uint32_t*)(smc + sw) = *(uint32_t*)&hh;
        }
    }
    __syncthreads();

    // ---------------- PASS 1: 4 tiles back-to-back, NO barriers ----------------
    #pragma unroll 1
    for (int t = 0; t < 4; t++) {
        uint32_t Abase = sbase + (t * 128 + m0 + rowAoff + r8) * 128;
        int bt = ((b * 4 + mg) * 4 + ng) * 4 + t;
        float sm[4] = {0.f, 0.f, 0.f, 0.f};

        #pragma unroll
        for (int mb = 0; mb < 2; mb++) {
            // load this m-block's A fragments ONCE (shared across both ch chunks)
            uint32_t ah[4][4];
            #pragma unroll
            for (int ks = 0; ks < 4; ks++) {
                uint32_t axor = (uint32_t)(((2 * ks + kcA) ^ r8) << 4);
                ldsm4(ah[ks][0], ah[ks][1], ah[ks][2], ah[ks][3], Abase + mb * 2048 + axor);
            }
            #pragma unroll
            for (int ch = 0; ch < 2; ch++) {
                int n0 = n0base + ch * 32;
                // coalesced kk fragment loads: 2x LDG.128 (at point of use — R15 best)
                const uint4* kb = (const uint4*)d_kkp + ((size_t)((bt * 2 + mb) * 2 + ch) * 2 * 32 + lane);
                uint4 kr0 = kb[0], kr1 = kb[32];
                float acc[4][4];
                #pragma unroll
                for (int q = 0; q < 4; q++)
                    #pragma unroll
                    for (int r = 0; r < 4; r++) acc[q][r] = 0.f;

                #pragma unroll
                for (int ks = 0; ks < 4; ks++) {
                    #pragma unroll
                    for (int nb = 0; nb < 2; nb++) {
                        mma16816(acc[2 * nb],     ah[ks], Breg[ch][nb][ks][0], Breg[ch][nb][ks][1]);
                        mma16816(acc[2 * nb + 1], ah[ks], Breg[ch][nb][ks][2], Breg[ch][nb][ks][3]);
                    }
                }
                // epilogue for this 32-col chunk
                float s0 = 0.f, s1 = 0.f;
                #pragma unroll
                for (int n8 = 0; n8 < 4; n8++) {
                    int n = n0 + n8 * 8 + t4 * 2;
                    float2 qv = *(const float2*)(qs + n);
                    float2 wv = *(const float2*)(w2s + n);
                    float2 k0 = __bfloat1622float2(*(const __nv_bfloat162*)&((const uint32_t*)&kr0)[n8]);
                    float2 k1 = __bfloat1622float2(*(const __nv_bfloat162*)&((const uint32_t*)&kr1)[n8]);
                    s0 = fmaf(fmaxf(acc[n8][0] + qv.x - k0.x, 0.f), wv.x,
                         fmaf(fmaxf(acc[n8][1] + qv.y - k0.y, 0.f), wv.y, s0));
                    s1 = fmaf(fmaxf(acc[n8][2] + qv.x - k1.x, 0.f), wv.x,
                         fmaf(fmaxf(acc[n8][3] + qv.y - k1.y, 0.f), wv.y, s1));
                }
                sm[2 * mb] += s0; sm[2 * mb + 1] += s1;
            }
        }
        // quad reduce + write per-tile partials (disjoint slots, no barrier)
        #pragma unroll
        for (int q = 0; q < 4; q++) {
            sm[q] += __shfl_xor_sync(0xffffffffu, sm[q], 1);
            sm[q] += __shfl_xor_sync(0xffffffffu, sm[q], 2);
        }
        if (t4 == 0) {
            spart[ng * 512 + t * 128 + m0 + rq]      = sm[0];
            spart[ng * 512 + t * 128 + m0 + rq + 8]  = sm[1];
            spart[ng * 512 + t * 128 + m0 + rq + 16] = sm[2];
            spart[ng * 512 + t * 128 + m0 + rq + 24] = sm[3];
        }
    }
    __syncthreads();

    // ---------------- softmax over 512 sims (reduction fused into read) ----------------
    {
        float s = spart[tid] + spart[512 + tid] + spart[1024 + tid] + spart[1536 + tid];
        float m = s;
        #pragma unroll
        for (int off = 16; off; off >>= 1) m = fmaxf(m, __shfl_xor_sync(0xffffffffu, m, off));
        if (lane == 0) red[wid] = m;
        __syncthreads();
        if (tid < 32) {
            float v = (tid < 16) ? red[tid] : -3.4e38f;
            #pragma unroll
            for (int off = 8; off; off >>= 1) v = fmaxf(v, __shfl_xor_sync(0xffffffffu, v, off));
            if (tid == 0) red[32] = v;
        }
        __syncthreads();
        float e = __expf(s - red[32]);
        float tt = e;
        #pragma unroll
        for (int off = 16; off; off >>= 1) tt += __shfl_xor_sync(0xffffffffu, tt, off);
        if (lane == 0) red[wid] = tt;
        __syncthreads();
        if (tid < 32) {
            float v = (tid < 16) ? red[tid] : 0.f;
            #pragma unroll
            for (int off = 8; off; off >>= 1) v += __shfl_xor_sync(0xffffffffu, v, off);
            if (tid == 0) red[33] = v;
        }
        __syncthreads();
        sims[tid] = e / red[33];
        __syncthreads();
    }

    // ---------------- PASS 2: k-pair per thread; g = a@p, r = a@v ----------------
    {
        int k2 = tid & 31, jg = tid >> 5;   // 16 j-groups of 32 rows
        int k = k2 << 1;
        float wx0 = w1s[k],     wy0 = w1s[64 + k],     wz0 = w1s[128 + k],     bb0 = b1s[k];
        float wx1 = w1s[k + 1], wy1 = w1s[64 + k + 1], wz1 = w1s[128 + k + 1], bb1 = b1s[k + 1];
        float g0 = 0.f, g1 = 0.f, r0 = 0.f, r1 = 0.f;
        const float* vb = d_v + ((size_t)(b << 9) + jg * 32) * 64 + k;
        int j0 = jg * 32;
        #pragma unroll 4
        for (int jj = 0; jj < 32; jj++) {
            int j = j0 + jj;
            float a = sims[j];
            float2 vv = *(const float2*)(vb + jj * 64);
            float rx = px - pjall[j], ry = py - pjall[512 + j], rz = pz - pjall[1024 + j];
            float pv0 = fmaxf(fmaf(rx, wx0, fmaf(ry, wy0, fmaf(rz, wz0, bb0))), 0.f);
            float pv1 = fmaxf(fmaf(rx, wx1, fmaf(ry, wy1, fmaf(rz, wz1, bb1))), 0.f);
            g0 = fmaf(a, pv0, g0); g1 = fmaf(a, pv1, g1);
            r0 = fmaf(a, vv.x, r0); r1 = fmaf(a, vv.y, r1);
        }
        *(float2*)(gpart + jg * 64 + k) = make_float2(g0, g1);
        *(float2*)(rpart + jg * 64 + k) = make_float2(r0, r1);
        __syncthreads();
        float rsum = 0.f;
        if (tid < 64) {
            float gsum = 0.f;
            #pragma unroll
            for (int w = 0; w < 16; w++) { gsum += gpart[w * 64 + tid]; rsum += rpart[w * 64 + tid]; }
            gs[tid] = gsum;
        }
        __syncthreads();
        if (tid < 64) {
            float o = rsum + pos_b2[tid];
            #pragma unroll 8
            for (int kk = 0; kk < 64; kk++) o = fmaf(gs[kk], pos_w2[kk * 64 + tid], o);
            out[(size_t)bi * 64 + tid] = o;
        }
    }
}

// -------------------- launch --------------------
extern "C" void kernel_launch(void* const* d_in, const int* in_sizes, int n_in,
                              void* d_out, int out_size) {
    const float* x       = (const float*)d_in[0];
    const float* pos     = (const float*)d_in[1];
    const float* w_qkv   = (const float*)d_in[2];
    const float* pos_w1  = (const float*)d_in[3];
    const float* pos_b1  = (const float*)d_in[4];
    const float* pos_w2  = (const float*)d_in[5];
    const float* pos_b2  = (const float*)d_in[6];
    const float* attn_w1 = (const float*)d_in[7];
    const float* attn_b1 = (const float*)d_in[8];
    const float* attn_w2 = (const float*)d_in[9];
    // attn_b2 (d_in[10]) cancels in softmax
    float* out = (float*)d_out;

    cudaFuncSetAttribute(pt_main, cudaFuncAttributeMaxDynamicSharedMemorySize, SMEM_TOTAL);

    prep_mats<<<193, 256>>>(w_qkv, pos_w2, pos_b2, attn_w1, attn_b1);
    proj_kernel<<<128, 256>>>(x, w_qkv);
    pt_main<<<NB * NSEQ, NT, SMEM_TOTAL>>>(pos, pos_w1, pos_b1, pos_w2, pos_b2, attn_w2, out);
}